// round 1
// baseline (speedup 1.0000x reference)
#include <cuda_runtime.h>
#include <cstdint>

#define Bb 2
#define Nn 2048
#define Cc 384
#define Hh 6
#define Dd 64
#define BN 4096
#define C3 1152
#define BHh 12

// ---- scratch (device globals; no runtime allocation) ----
__device__ int8_t g_xq[BN * Cc];
__device__ int8_t g_wqkv[C3 * Cc];
__device__ int8_t g_wproj[Cc * Cc];
__device__ int8_t g_q[BHh * Nn * Dd];    // [b,h,n,d]
__device__ int8_t g_k[BHh * Nn * Dd];    // [b,h,n,d]
__device__ int8_t g_vT[BHh * Dd * Nn];   // [b,h,d,n]  (transposed for PV mma B operand)
__device__ int8_t g_p[(long long)BHh * Nn * Nn];  // quantized attention probs
__device__ int8_t g_o[BN * Cc];          // attention output, quantized with a_proj_a

// clip-then-round (matches jnp.clip -> jnp.round, both round-half-even)
__device__ __forceinline__ float q8f(float v, float alpha) {
    return rintf(fminf(fmaxf(v / alpha, -128.f), 127.f));
}

__device__ __forceinline__ void mma8(int* c, const unsigned* a, const unsigned* b) {
    asm volatile(
        "mma.sync.aligned.m16n8k32.row.col.s32.s8.s8.s32 "
        "{%0,%1,%2,%3}, {%4,%5,%6,%7}, {%8,%9}, {%0,%1,%2,%3};\n"
        : "+r"(c[0]), "+r"(c[1]), "+r"(c[2]), "+r"(c[3])
        : "r"(a[0]), "r"(a[1]), "r"(a[2]), "r"(a[3]), "r"(b[0]), "r"(b[1]));
}

// ---------------- quantize kernels ----------------
#define QUANT_KERNEL(NAME, DST)                                              \
__global__ void NAME(const float* __restrict__ x, const float* __restrict__ al) { \
    int i = blockIdx.x * blockDim.x + threadIdx.x;                           \
    float a = __ldg(al);                                                     \
    float4 v = ((const float4*)x)[i];                                        \
    char4 r;                                                                 \
    r.x = (char)(int)q8f(v.x, a); r.y = (char)(int)q8f(v.y, a);              \
    r.z = (char)(int)q8f(v.z, a); r.w = (char)(int)q8f(v.w, a);              \
    ((char4*)DST)[i] = r;                                                    \
}
QUANT_KERNEL(quant_x_k, g_xq)
QUANT_KERNEL(quant_wqkv_k, g_wqkv)
QUANT_KERNEL(quant_wproj_k, g_wproj)

// ---------------- GEMM1: qkv = xq @ wqkv^T, requant-split into q/k/vT ----------------
__global__ void __launch_bounds__(256) gemm_qkv_k(
    const float* al_a, const float* al_w,
    const float* al_q, const float* al_k, const float* al_v) {
    const int bm = blockIdx.y * 128;
    const int bn = blockIdx.x * 128;
    const int wid = threadIdx.x >> 5;
    const int lane = threadIdx.x & 31;
    const int wm = (wid & 3) * 32;
    const int wn = (wid >> 2) * 64;
    const int lr = lane >> 2;
    const int lc = (lane & 3) << 2;

    int c[2][8][4];
#pragma unroll
    for (int i = 0; i < 2; i++)
#pragma unroll
        for (int j = 0; j < 8; j++)
#pragma unroll
            for (int t = 0; t < 4; t++) c[i][j][t] = 0;

#pragma unroll 1
    for (int k0 = 0; k0 < Cc; k0 += 32) {
        unsigned a[2][4];
#pragma unroll
        for (int mt = 0; mt < 2; mt++) {
            const int8_t* ap = g_xq + (bm + wm + mt * 16 + lr) * Cc + k0 + lc;
            a[mt][0] = *(const unsigned*)(ap);
            a[mt][1] = *(const unsigned*)(ap + 8 * Cc);
            a[mt][2] = *(const unsigned*)(ap + 16);
            a[mt][3] = *(const unsigned*)(ap + 8 * Cc + 16);
        }
#pragma unroll
        for (int nt = 0; nt < 8; nt++) {
            const int8_t* bp = g_wqkv + (bn + wn + nt * 8 + lr) * Cc + k0 + lc;
            unsigned bb[2] = {*(const unsigned*)bp, *(const unsigned*)(bp + 16)};
            mma8(c[0][nt], a[0], bb);
            mma8(c[1][nt], a[1], bb);
        }
    }

    const float c1 = __ldg(al_a) * __ldg(al_w);
    const float aq = __ldg(al_q), ak = __ldg(al_k), av = __ldg(al_v);
#pragma unroll
    for (int mt = 0; mt < 2; mt++)
#pragma unroll
        for (int nt = 0; nt < 8; nt++)
#pragma unroll
            for (int j = 0; j < 4; j++) {
                int row = bm + wm + mt * 16 + lr + ((j >> 1) << 3);
                int col = bn + wn + nt * 8 + ((lane & 3) << 1) + (j & 1);
                float f = (float)c[mt][nt][j] * c1;
                int b = row >> 11, n = row & (Nn - 1);
                int which = col / Cc;
                int cr = col - which * Cc;
                int h = cr >> 6, d = cr & 63;
                if (which == 0)
                    g_q[((b * Hh + h) * Nn + n) * Dd + d] = (int8_t)(int)q8f(f, aq);
                else if (which == 1)
                    g_k[((b * Hh + h) * Nn + n) * Dd + d] = (int8_t)(int)q8f(f, ak);
                else
                    g_vT[((b * Hh + h) * Dd + d) * Nn + n] = (int8_t)(int)q8f(f, av);
            }
}

// ---------------- QK^T + quant + softmax + quant -> g_p ----------------
__global__ void __launch_bounds__(256) qk_softmax_k(
    const float* al_q, const float* al_k, const float* al_attn, const float* al_attn2) {
    extern __shared__ int8_t s_s[];  // [64][2048] quantized scores
    const int bh = blockIdx.y;
    const int rb = blockIdx.x * 64;
    const int8_t* qp = g_q + bh * Nn * Dd;
    const int8_t* kp = g_k + bh * Nn * Dd;
    const int wid = threadIdx.x >> 5;
    const int lane = threadIdx.x & 31;
    const int lr = lane >> 2;
    const int lc = (lane & 3) << 2;
    const float aAttn = __ldg(al_attn);
    const float c2 = __ldg(al_q) * __ldg(al_k) * 0.125f;  // scale = D^-0.5

    // preload q fragments for all 64 rows (shared by every n-stripe chunk)
    unsigned a[4][2][4];
#pragma unroll
    for (int mt = 0; mt < 4; mt++)
#pragma unroll
        for (int ks = 0; ks < 2; ks++) {
            const int8_t* ap = qp + (rb + mt * 16 + lr) * Dd + ks * 32 + lc;
            a[mt][ks][0] = *(const unsigned*)ap;
            a[mt][ks][1] = *(const unsigned*)(ap + 8 * Dd);
            a[mt][ks][2] = *(const unsigned*)(ap + 16);
            a[mt][ks][3] = *(const unsigned*)(ap + 8 * Dd + 16);
        }

    const int nbase = wid * 256;  // each warp owns a 256-wide column stripe
#pragma unroll 1
    for (int nc = 0; nc < 256; nc += 32) {
        int c[4][4][4];
#pragma unroll
        for (int i = 0; i < 4; i++)
#pragma unroll
            for (int j = 0; j < 4; j++)
#pragma unroll
                for (int t = 0; t < 4; t++) c[i][j][t] = 0;

#pragma unroll
        for (int nt = 0; nt < 4; nt++)
#pragma unroll
            for (int ks = 0; ks < 2; ks++) {
                const int8_t* bp = kp + (nbase + nc + nt * 8 + lr) * Dd + ks * 32 + lc;
                unsigned bb[2] = {*(const unsigned*)bp, *(const unsigned*)(bp + 16)};
#pragma unroll
                for (int mt = 0; mt < 4; mt++) mma8(c[mt][nt], a[mt][ks], bb);
            }
        // quantize scores with a_attn into smem (int8)
#pragma unroll
        for (int mt = 0; mt < 4; mt++)
#pragma unroll
            for (int nt = 0; nt < 4; nt++)
#pragma unroll
                for (int jj = 0; jj < 2; jj++) {
                    int row = mt * 16 + lr + jj * 8;
                    int col = nbase + nc + nt * 8 + ((lane & 3) << 1);
                    char2 o;
                    o.x = (char)(int)q8f((float)c[mt][nt][jj * 2 + 0] * c2, aAttn);
                    o.y = (char)(int)q8f((float)c[mt][nt][jj * 2 + 1] * c2, aAttn);
                    *(char2*)(s_s + row * Nn + col) = o;
                }
    }
    __syncthreads();

    // softmax over each row, quantize with a_attn2, write to gmem
    const float a2 = __ldg(al_attn2);
#pragma unroll 1
    for (int r = wid * 8; r < wid * 8 + 8; r++) {
        const int8_t* srow = s_s + r * Nn;
        unsigned mx4 = 0x80808080u;
        for (int i = lane * 4; i < Nn; i += 128)
            mx4 = __vmaxs4(mx4, *(const unsigned*)(srow + i));
#pragma unroll
        for (int off = 16; off; off >>= 1)
            mx4 = __vmaxs4(mx4, __shfl_xor_sync(0xffffffffu, mx4, off));
        int m = -128;
#pragma unroll
        for (int t = 0; t < 4; t++) m = max(m, (int)(char)(mx4 >> (t * 8)));

        float sum = 0.f;
        for (int i = lane * 4; i < Nn; i += 128) {
            unsigned w = *(const unsigned*)(srow + i);
            sum += expf(aAttn * (float)((int)(char)(w) - m));
            sum += expf(aAttn * (float)((int)(char)(w >> 8) - m));
            sum += expf(aAttn * (float)((int)(char)(w >> 16) - m));
            sum += expf(aAttn * (float)((int)(char)(w >> 24) - m));
        }
#pragma unroll
        for (int off = 16; off; off >>= 1)
            sum += __shfl_xor_sync(0xffffffffu, sum, off);
        const float inv = 1.f / (sum * a2);

        int8_t* prow = g_p + ((long long)bh * Nn + rb + r) * Nn;
        for (int i = lane * 4; i < Nn; i += 128) {
            unsigned w = *(const unsigned*)(srow + i);
            char4 o;
            o.x = (char)(int)rintf(fminf(expf(aAttn * (float)((int)(char)(w) - m)) * inv, 127.f));
            o.y = (char)(int)rintf(fminf(expf(aAttn * (float)((int)(char)(w >> 8) - m)) * inv, 127.f));
            o.z = (char)(int)rintf(fminf(expf(aAttn * (float)((int)(char)(w >> 16) - m)) * inv, 127.f));
            o.w = (char)(int)rintf(fminf(expf(aAttn * (float)((int)(char)(w >> 24) - m)) * inv, 127.f));
            *(char4*)(prow + i) = o;
        }
    }
}

// ---------------- PV: out = p @ v, requant with a_proj_a -> g_o ----------------
__global__ void __launch_bounds__(256) pv_k(
    const float* al_attn2, const float* al_v, const float* al_pa) {
    const int bh = blockIdx.y;
    const int bm = blockIdx.x * 128;
    const int8_t* P = g_p + (long long)bh * Nn * Nn;
    const int8_t* Vt = g_vT + bh * Dd * Nn;
    const int wid = threadIdx.x >> 5, lane = threadIdx.x & 31;
    const int wm = (wid & 3) * 32, wn = (wid >> 2) * 32;
    const int lr = lane >> 2, lc = (lane & 3) << 2;

    int c[2][4][4];
#pragma unroll
    for (int i = 0; i < 2; i++)
#pragma unroll
        for (int j = 0; j < 4; j++)
#pragma unroll
            for (int t = 0; t < 4; t++) c[i][j][t] = 0;

#pragma unroll 1
    for (int k0 = 0; k0 < Nn; k0 += 32) {
        unsigned a[2][4];
#pragma unroll
        for (int mt = 0; mt < 2; mt++) {
            const int8_t* ap = P + (bm + wm + mt * 16 + lr) * Nn + k0 + lc;
            a[mt][0] = *(const unsigned*)ap;
            a[mt][1] = *(const unsigned*)(ap + 8 * Nn);
            a[mt][2] = *(const unsigned*)(ap + 16);
            a[mt][3] = *(const unsigned*)(ap + 8 * Nn + 16);
        }
#pragma unroll
        for (int nt = 0; nt < 4; nt++) {
            const int8_t* bp = Vt + (wn + nt * 8 + lr) * Nn + k0 + lc;
            unsigned bb[2] = {*(const unsigned*)bp, *(const unsigned*)(bp + 16)};
            mma8(c[0][nt], a[0], bb);
            mma8(c[1][nt], a[1], bb);
        }
    }

    const float c3 = __ldg(al_attn2) * __ldg(al_v);
    const float apa = __ldg(al_pa);
    const int b = bh / Hh, h = bh % Hh;
#pragma unroll
    for (int mt = 0; mt < 2; mt++)
#pragma unroll
        for (int nt = 0; nt < 4; nt++)
#pragma unroll
            for (int j = 0; j < 4; j++) {
                int n = bm + wm + mt * 16 + lr + ((j >> 1) << 3);
                int d = wn + nt * 8 + ((lane & 3) << 1) + (j & 1);
                float f = (float)c[mt][nt][j] * c3;
                g_o[(b * Nn + n) * Cc + h * Dd + d] = (int8_t)(int)q8f(f, apa);
            }
}

// ---------------- GEMM2: final projection + bias -> fp32 out ----------------
__global__ void __launch_bounds__(256) gemm_proj_k(
    float* __restrict__ out, const float* __restrict__ bias,
    const float* al_pa, const float* al_pw) {
    const int bm = blockIdx.y * 128;
    const int bn = blockIdx.x * 128;
    const int wid = threadIdx.x >> 5;
    const int lane = threadIdx.x & 31;
    const int wm = (wid & 3) * 32;
    const int wn = (wid >> 2) * 64;
    const int lr = lane >> 2;
    const int lc = (lane & 3) << 2;

    int c[2][8][4];
#pragma unroll
    for (int i = 0; i < 2; i++)
#pragma unroll
        for (int j = 0; j < 8; j++)
#pragma unroll
            for (int t = 0; t < 4; t++) c[i][j][t] = 0;

#pragma unroll 1
    for (int k0 = 0; k0 < Cc; k0 += 32) {
        unsigned a[2][4];
#pragma unroll
        for (int mt = 0; mt < 2; mt++) {
            const int8_t* ap = g_o + (bm + wm + mt * 16 + lr) * Cc + k0 + lc;
            a[mt][0] = *(const unsigned*)(ap);
            a[mt][1] = *(const unsigned*)(ap + 8 * Cc);
            a[mt][2] = *(const unsigned*)(ap + 16);
            a[mt][3] = *(const unsigned*)(ap + 8 * Cc + 16);
        }
#pragma unroll
        for (int nt = 0; nt < 8; nt++) {
            const int8_t* bp = g_wproj + (bn + wn + nt * 8 + lr) * Cc + k0 + lc;
            unsigned bb[2] = {*(const unsigned*)bp, *(const unsigned*)(bp + 16)};
            mma8(c[0][nt], a[0], bb);
            mma8(c[1][nt], a[1], bb);
        }
    }

    const float sc = __ldg(al_pa) * __ldg(al_pw);
#pragma unroll
    for (int mt = 0; mt < 2; mt++)
#pragma unroll
        for (int nt = 0; nt < 8; nt++)
#pragma unroll
            for (int j = 0; j < 4; j++) {
                int row = bm + wm + mt * 16 + lr + ((j >> 1) << 3);
                int col = bn + wn + nt * 8 + ((lane & 3) << 1) + (j & 1);
                out[row * Cc + col] = (float)c[mt][nt][j] * sc + __ldg(bias + col);
            }
}

extern "C" void kernel_launch(void* const* d_in, const int* in_sizes, int n_in,
                              void* d_out, int out_size) {
    const float* x        = (const float*)d_in[0];
    const float* w_qkv    = (const float*)d_in[1];
    const float* w_proj   = (const float*)d_in[2];
    const float* b_proj   = (const float*)d_in[3];
    const float* a_qkv_w  = (const float*)d_in[4];
    const float* a_qkv_a  = (const float*)d_in[5];
    const float* a_proj_w = (const float*)d_in[6];
    const float* a_proj_a = (const float*)d_in[7];
    const float* a_q      = (const float*)d_in[8];
    const float* a_k      = (const float*)d_in[9];
    const float* a_v      = (const float*)d_in[10];
    const float* a_attn   = (const float*)d_in[11];
    const float* a_attn2  = (const float*)d_in[12];
    float* out = (float*)d_out;

    quant_x_k<<<BN * Cc / 4 / 256, 256>>>(x, a_qkv_a);
    quant_wqkv_k<<<C3 * Cc / 4 / 256, 256>>>(w_qkv, a_qkv_w);
    quant_wproj_k<<<Cc * Cc / 4 / 256, 256>>>(w_proj, a_proj_w);

    gemm_qkv_k<<<dim3(C3 / 128, BN / 128), 256>>>(a_qkv_a, a_qkv_w, a_q, a_k, a_v);

    cudaFuncSetAttribute(qk_softmax_k, cudaFuncAttributeMaxDynamicSharedMemorySize, 64 * Nn);
    qk_softmax_k<<<dim3(Nn / 64, BHh), 256, 64 * Nn>>>(a_q, a_k, a_attn, a_attn2);

    pv_k<<<dim3(Nn / 128, BHh), 256>>>(a_attn2, a_v, a_proj_a);

    gemm_proj_k<<<dim3(Cc / 128, BN / 128), 256>>>(out, b_proj, a_proj_a, a_proj_w);
}

// round 2
// speedup vs baseline: 1.6441x; 1.6441x over previous
#include <cuda_runtime.h>
#include <cstdint>

#define Bb 2
#define Nn 2048
#define Cc 384
#define Hh 6
#define Dd 64
#define BN 4096
#define C3 1152
#define BHh 12
#define SROW 2064   // padded smem row stride (bytes) -> conflict-free PV LDS

// ---- scratch (device globals; no runtime allocation) ----
__device__ int8_t g_xq[BN * Cc];
__device__ int8_t g_wqkv[C3 * Cc];
__device__ int8_t g_wproj[Cc * Cc];
__device__ int8_t g_q[BHh * Nn * Dd];    // [b,h,n,d]
__device__ int8_t g_k[BHh * Nn * Dd];    // [b,h,n,d]
__device__ int8_t g_vT[BHh * Dd * Nn];   // [b,h,d,n]
__device__ int8_t g_o[BN * Cc];          // attention output, quantized with a_proj_a

__device__ __forceinline__ float q8m(float v, float inv_alpha) {
    return rintf(fminf(fmaxf(v * inv_alpha, -128.f), 127.f));
}

__device__ __forceinline__ void mma8(int* c, const unsigned* a, const unsigned* b) {
    asm volatile(
        "mma.sync.aligned.m16n8k32.row.col.s32.s8.s8.s32 "
        "{%0,%1,%2,%3}, {%4,%5,%6,%7}, {%8,%9}, {%0,%1,%2,%3};\n"
        : "+r"(c[0]), "+r"(c[1]), "+r"(c[2]), "+r"(c[3])
        : "r"(a[0]), "r"(a[1]), "r"(a[2]), "r"(a[3]), "r"(b[0]), "r"(b[1]));
}

// ---------------- quantize kernels ----------------
#define QUANT_KERNEL(NAME, DST)                                              \
__global__ void NAME(const float* __restrict__ x, const float* __restrict__ al) { \
    int i = blockIdx.x * blockDim.x + threadIdx.x;                           \
    float ia = 1.f / __ldg(al);                                              \
    float4 v = ((const float4*)x)[i];                                        \
    char4 r;                                                                 \
    r.x = (char)(int)q8m(v.x, ia); r.y = (char)(int)q8m(v.y, ia);            \
    r.z = (char)(int)q8m(v.z, ia); r.w = (char)(int)q8m(v.w, ia);            \
    ((char4*)DST)[i] = r;                                                    \
}
QUANT_KERNEL(quant_x_k, g_xq)
QUANT_KERNEL(quant_wqkv_k, g_wqkv)
QUANT_KERNEL(quant_wproj_k, g_wproj)

// ---------------- GEMM1: qkv = xq @ wqkv^T, requant-split into q/k/vT ----------------
__global__ void __launch_bounds__(256) gemm_qkv_k(
    const float* al_a, const float* al_w,
    const float* al_q, const float* al_k, const float* al_v) {
    const int bm = blockIdx.y * 128;
    const int bn = blockIdx.x * 128;
    const int wid = threadIdx.x >> 5;
    const int lane = threadIdx.x & 31;
    const int wm = (wid & 3) * 32;
    const int wn = (wid >> 2) * 64;
    const int lr = lane >> 2;
    const int lc = (lane & 3) << 2;

    int c[2][8][4];
#pragma unroll
    for (int i = 0; i < 2; i++)
#pragma unroll
        for (int j = 0; j < 8; j++)
#pragma unroll
            for (int t = 0; t < 4; t++) c[i][j][t] = 0;

#pragma unroll 2
    for (int k0 = 0; k0 < Cc; k0 += 32) {
        unsigned a[2][4];
#pragma unroll
        for (int mt = 0; mt < 2; mt++) {
            const int8_t* ap = g_xq + (bm + wm + mt * 16 + lr) * Cc + k0 + lc;
            a[mt][0] = *(const unsigned*)(ap);
            a[mt][1] = *(const unsigned*)(ap + 8 * Cc);
            a[mt][2] = *(const unsigned*)(ap + 16);
            a[mt][3] = *(const unsigned*)(ap + 8 * Cc + 16);
        }
#pragma unroll
        for (int nt = 0; nt < 8; nt++) {
            const int8_t* bp = g_wqkv + (bn + wn + nt * 8 + lr) * Cc + k0 + lc;
            unsigned bb[2] = {*(const unsigned*)bp, *(const unsigned*)(bp + 16)};
            mma8(c[0][nt], a[0], bb);
            mma8(c[1][nt], a[1], bb);
        }
    }

    const float c1 = __ldg(al_a) * __ldg(al_w);
    const float iq = c1 / __ldg(al_q), ik = c1 / __ldg(al_k), iv = c1 / __ldg(al_v);
#pragma unroll
    for (int mt = 0; mt < 2; mt++)
#pragma unroll
        for (int nt = 0; nt < 8; nt++)
#pragma unroll
            for (int j = 0; j < 4; j++) {
                int row = bm + wm + mt * 16 + lr + ((j >> 1) << 3);
                int col = bn + wn + nt * 8 + ((lane & 3) << 1) + (j & 1);
                float f = (float)c[mt][nt][j];
                int b = row >> 11, n = row & (Nn - 1);
                int which = col / Cc;
                int cr = col - which * Cc;
                int h = cr >> 6, d = cr & 63;
                if (which == 0)
                    g_q[((b * Hh + h) * Nn + n) * Dd + d] = (int8_t)(int)q8m(f, iq);
                else if (which == 1)
                    g_k[((b * Hh + h) * Nn + n) * Dd + d] = (int8_t)(int)q8m(f, ik);
                else
                    g_vT[((b * Hh + h) * Dd + d) * Nn + n] = (int8_t)(int)q8m(f, iv);
            }
}

// ---------------- fused: QK^T -> quant -> softmax -> quant -> P@V -> quant -> g_o ----
__global__ void __launch_bounds__(256, 2) attn_fused_k(
    const float* al_q, const float* al_k, const float* al_attn, const float* al_attn2,
    const float* al_v, const float* al_pa) {
    extern __shared__ int8_t s_s[];  // [32][SROW] scores, then quantized probs
    const int bh = blockIdx.y;
    const int rb = blockIdx.x * 32;
    const int8_t* qp = g_q + bh * Nn * Dd;
    const int8_t* kp = g_k + bh * Nn * Dd;
    const int wid = threadIdx.x >> 5;
    const int lane = threadIdx.x & 31;
    const int lr = lane >> 2;
    const int lc = (lane & 3) << 2;
    const float aAttn = __ldg(al_attn);
    // combined: int_score * (aq*ak*D^-0.5 / aAttn), then rint+clamp
    const float c2i = __ldg(al_q) * __ldg(al_k) * 0.125f / aAttn;

    // ---- Phase A: QK^T, quantize scores into smem ----
    // preload q fragments for the 32 rows (2 m-tiles), K=64 (2 k-steps)
    unsigned a[2][2][4];
#pragma unroll
    for (int mt = 0; mt < 2; mt++)
#pragma unroll
        for (int ks = 0; ks < 2; ks++) {
            const int8_t* ap = qp + (rb + mt * 16 + lr) * Dd + ks * 32 + lc;
            a[mt][ks][0] = *(const unsigned*)ap;
            a[mt][ks][1] = *(const unsigned*)(ap + 8 * Dd);
            a[mt][ks][2] = *(const unsigned*)(ap + 16);
            a[mt][ks][3] = *(const unsigned*)(ap + 8 * Dd + 16);
        }

    const int nbase = wid * 256;  // each warp owns a 256-wide column stripe
#pragma unroll 1
    for (int nc = 0; nc < 256; nc += 32) {
        int c[2][4][4];
#pragma unroll
        for (int i = 0; i < 2; i++)
#pragma unroll
            for (int j = 0; j < 4; j++)
#pragma unroll
                for (int t = 0; t < 4; t++) c[i][j][t] = 0;

#pragma unroll
        for (int nt = 0; nt < 4; nt++)
#pragma unroll
            for (int ks = 0; ks < 2; ks++) {
                const int8_t* bp = kp + (nbase + nc + nt * 8 + lr) * Dd + ks * 32 + lc;
                unsigned bb[2] = {*(const unsigned*)bp, *(const unsigned*)(bp + 16)};
                mma8(c[0][nt], a[0][ks], bb);
                mma8(c[1][nt], a[1][ks], bb);
            }
#pragma unroll
        for (int mt = 0; mt < 2; mt++)
#pragma unroll
            for (int nt = 0; nt < 4; nt++)
#pragma unroll
                for (int jj = 0; jj < 2; jj++) {
                    int row = mt * 16 + lr + jj * 8;
                    int col = nbase + nc + nt * 8 + ((lane & 3) << 1);
                    char2 o;
                    o.x = (char)(int)q8m((float)c[mt][nt][jj * 2 + 0], c2i);
                    o.y = (char)(int)q8m((float)c[mt][nt][jj * 2 + 1], c2i);
                    *(char2*)(s_s + row * SROW + col) = o;
                }
    }
    __syncthreads();

    // ---- Phase B: softmax per row (no max pass; args bounded), quantize in place ----
    {
        const float k2 = aAttn * 1.44269504f;       // exp(aAttn*t) = exp2(k2*t)
        const float a2 = __ldg(al_attn2);
#pragma unroll 1
        for (int r = wid * 4; r < wid * 4 + 4; r++) {
            int8_t* srow = s_s + r * SROW;
            float ex[64];
            float sum = 0.f;
#pragma unroll
            for (int it = 0; it < 16; it++) {
                unsigned w = *(const unsigned*)(srow + lane * 4 + it * 128);
#pragma unroll
                for (int t = 0; t < 4; t++) {
                    float e = exp2f(k2 * (float)(int)(char)(w >> (8 * t)));
                    ex[it * 4 + t] = e;
                    sum += e;
                }
            }
#pragma unroll
            for (int off = 16; off; off >>= 1)
                sum += __shfl_xor_sync(0xffffffffu, sum, off);
            const float inv = 1.f / (sum * a2);
#pragma unroll
            for (int it = 0; it < 16; it++) {
                char4 o;
                o.x = (char)(int)rintf(fminf(ex[it * 4 + 0] * inv, 127.f));
                o.y = (char)(int)rintf(fminf(ex[it * 4 + 1] * inv, 127.f));
                o.z = (char)(int)rintf(fminf(ex[it * 4 + 2] * inv, 127.f));
                o.w = (char)(int)rintf(fminf(ex[it * 4 + 3] * inv, 127.f));
                *(char4*)(srow + lane * 4 + it * 128) = o;
            }
        }
    }
    __syncthreads();

    // ---- Phase C: out = P @ V (A from smem, B = vT from gmem/L2), requant -> g_o ----
    {
        const int8_t* Vt = g_vT + bh * Dd * Nn;
        const int wm2 = (wid & 1) * 16;
        const int wn2 = (wid >> 1) * 16;
        int c[2][4];
#pragma unroll
        for (int i = 0; i < 2; i++)
#pragma unroll
            for (int t = 0; t < 4; t++) c[i][t] = 0;

#pragma unroll 2
        for (int k0 = 0; k0 < Nn; k0 += 32) {
            unsigned af[4];
            const int8_t* ap = s_s + (wm2 + lr) * SROW + k0 + lc;
            af[0] = *(const unsigned*)ap;
            af[1] = *(const unsigned*)(ap + 8 * SROW);
            af[2] = *(const unsigned*)(ap + 16);
            af[3] = *(const unsigned*)(ap + 8 * SROW + 16);
#pragma unroll
            for (int nt = 0; nt < 2; nt++) {
                const int8_t* bp = Vt + (wn2 + nt * 8 + lr) * Nn + k0 + lc;
                unsigned bb[2] = {*(const unsigned*)bp, *(const unsigned*)(bp + 16)};
                mma8(c[nt], af, bb);
            }
        }

        const float c3 = __ldg(al_attn2) * __ldg(al_v);
        const float ipa = c3 / __ldg(al_pa);
        const int b = bh / Hh, h = bh % Hh;
#pragma unroll
        for (int nt = 0; nt < 2; nt++)
#pragma unroll
            for (int j = 0; j < 4; j++) {
                int n = rb + wm2 + lr + ((j >> 1) << 3);
                int d = wn2 + nt * 8 + ((lane & 3) << 1) + (j & 1);
                g_o[(b * Nn + n) * Cc + h * Dd + d] =
                    (int8_t)(int)q8m((float)c[nt][j], ipa);
            }
    }
}

// ---------------- GEMM2: final projection + bias -> fp32 out ----------------
__global__ void __launch_bounds__(256) gemm_proj_k(
    float* __restrict__ out, const float* __restrict__ bias,
    const float* al_pa, const float* al_pw) {
    const int bm = blockIdx.y * 128;
    const int bn = blockIdx.x * 128;
    const int wid = threadIdx.x >> 5;
    const int lane = threadIdx.x & 31;
    const int wm = (wid & 3) * 32;
    const int wn = (wid >> 2) * 64;
    const int lr = lane >> 2;
    const int lc = (lane & 3) << 2;

    int c[2][8][4];
#pragma unroll
    for (int i = 0; i < 2; i++)
#pragma unroll
        for (int j = 0; j < 8; j++)
#pragma unroll
            for (int t = 0; t < 4; t++) c[i][j][t] = 0;

#pragma unroll 2
    for (int k0 = 0; k0 < Cc; k0 += 32) {
        unsigned a[2][4];
#pragma unroll
        for (int mt = 0; mt < 2; mt++) {
            const int8_t* ap = g_o + (bm + wm + mt * 16 + lr) * Cc + k0 + lc;
            a[mt][0] = *(const unsigned*)(ap);
            a[mt][1] = *(const unsigned*)(ap + 8 * Cc);
            a[mt][2] = *(const unsigned*)(ap + 16);
            a[mt][3] = *(const unsigned*)(ap + 8 * Cc + 16);
        }
#pragma unroll
        for (int nt = 0; nt < 8; nt++) {
            const int8_t* bp = g_wproj + (bn + wn + nt * 8 + lr) * Cc + k0 + lc;
            unsigned bb[2] = {*(const unsigned*)bp, *(const unsigned*)(bp + 16)};
            mma8(c[0][nt], a[0], bb);
            mma8(c[1][nt], a[1], bb);
        }
    }

    const float sc = __ldg(al_pa) * __ldg(al_pw);
#pragma unroll
    for (int mt = 0; mt < 2; mt++)
#pragma unroll
        for (int nt = 0; nt < 8; nt++)
#pragma unroll
            for (int j = 0; j < 4; j++) {
                int row = bm + wm + mt * 16 + lr + ((j >> 1) << 3);
                int col = bn + wn + nt * 8 + ((lane & 3) << 1) + (j & 1);
                out[row * Cc + col] = (float)c[mt][nt][j] * sc + __ldg(bias + col);
            }
}

extern "C" void kernel_launch(void* const* d_in, const int* in_sizes, int n_in,
                              void* d_out, int out_size) {
    const float* x        = (const float*)d_in[0];
    const float* w_qkv    = (const float*)d_in[1];
    const float* w_proj   = (const float*)d_in[2];
    const float* b_proj   = (const float*)d_in[3];
    const float* a_qkv_w  = (const float*)d_in[4];
    const float* a_qkv_a  = (const float*)d_in[5];
    const float* a_proj_w = (const float*)d_in[6];
    const float* a_proj_a = (const float*)d_in[7];
    const float* a_q      = (const float*)d_in[8];
    const float* a_k      = (const float*)d_in[9];
    const float* a_v      = (const float*)d_in[10];
    const float* a_attn   = (const float*)d_in[11];
    const float* a_attn2  = (const float*)d_in[12];
    float* out = (float*)d_out;

    quant_x_k<<<BN * Cc / 4 / 256, 256>>>(x, a_qkv_a);
    quant_wqkv_k<<<C3 * Cc / 4 / 256, 256>>>(w_qkv, a_qkv_w);
    quant_wproj_k<<<Cc * Cc / 4 / 256, 256>>>(w_proj, a_proj_w);

    gemm_qkv_k<<<dim3(C3 / 128, BN / 128), 256>>>(a_qkv_a, a_qkv_w, a_q, a_k, a_v);

    cudaFuncSetAttribute(attn_fused_k, cudaFuncAttributeMaxDynamicSharedMemorySize, 32 * SROW);
    attn_fused_k<<<dim3(Nn / 32, BHh), 256, 32 * SROW>>>(a_q, a_k, a_attn, a_attn2, a_v, a_proj_a);

    gemm_proj_k<<<dim3(Cc / 128, BN / 128), 256>>>(out, b_proj, a_proj_a, a_proj_w);
}

// round 3
// speedup vs baseline: 1.9307x; 1.1743x over previous
#include <cuda_runtime.h>
#include <cstdint>

#define Bb 2
#define Nn 2048
#define Cc 384
#define Hh 6
#define Dd 64
#define BN 4096
#define C3 1152
#define BHh 12
#define SROW 2064   // padded smem row stride (bytes), mult of 16

// permute byte position within each 32-byte k-group so that the mma fragment
// pair (k+lc, k+16+lc) becomes 8 contiguous bytes (one LDG.64/LDS.64)
#define PHYS32(v) (((v) & ~31) | (((v) & 12) << 1) | (((v) & 16) >> 2) | ((v) & 3))

// ---- scratch (device globals; no runtime allocation) ----
__device__ int8_t g_xq[BN * Cc];
__device__ int8_t g_wqkv[C3 * Cc];
__device__ int8_t g_wproj[Cc * Cc];
__device__ int8_t g_q[BHh * Nn * Dd];    // [b,h,n,phys(d)]
__device__ int8_t g_k[BHh * Nn * Dd];    // [b,h,n,phys(d)]
__device__ int8_t g_vT[BHh * Dd * Nn];   // [b,h,d,phys(n)]
__device__ int8_t g_o[BN * Cc];          // [b,n, phys(h*64+d)], alpha = a_proj_a

__device__ __forceinline__ int q8i(float v) {
    return __float2int_rn(fminf(fmaxf(v, -128.f), 127.f));
}

__device__ __forceinline__ void mma8(int* c, const unsigned* a, const unsigned* b) {
    asm volatile(
        "mma.sync.aligned.m16n8k32.row.col.s32.s8.s8.s32 "
        "{%0,%1,%2,%3}, {%4,%5,%6,%7}, {%8,%9}, {%0,%1,%2,%3};\n"
        : "+r"(c[0]), "+r"(c[1]), "+r"(c[2]), "+r"(c[3])
        : "r"(a[0]), "r"(a[1]), "r"(a[2]), "r"(a[3]), "r"(b[0]), "r"(b[1]));
}

// ---------------- quantize kernels (write perm layout) ----------------
#define QUANT_KERNEL(NAME, DST)                                              \
__global__ void NAME(const float* __restrict__ x, const float* __restrict__ al) { \
    int i = blockIdx.x * blockDim.x + threadIdx.x;                           \
    float ia = 1.f / __ldg(al);                                              \
    float4 v = ((const float4*)x)[i];                                        \
    char4 r;                                                                 \
    r.x = (char)q8i(v.x * ia); r.y = (char)q8i(v.y * ia);                    \
    r.z = (char)q8i(v.z * ia); r.w = (char)q8i(v.w * ia);                    \
    int c4 = (i * 4) % Cc;                                                   \
    int row = (i * 4) / Cc;                                                  \
    int pc = (c4 & ~31) + (((c4 >> 2) & 3) << 3) + (((c4 >> 4) & 1) << 2);   \
    *(char4*)(DST + row * Cc + pc) = r;                                      \
}
QUANT_KERNEL(quant_x_k, g_xq)
QUANT_KERNEL(quant_wqkv_k, g_wqkv)
QUANT_KERNEL(quant_wproj_k, g_wproj)

// ---------------- GEMM1: qkv = xq @ wqkv^T, requant-split into q/k/vT ----------------
__global__ void __launch_bounds__(256) gemm_qkv_k(
    const float* al_a, const float* al_w,
    const float* al_q, const float* al_k, const float* al_v) {
    const int bm = blockIdx.y * 128;
    const int bn = blockIdx.x * 128;
    const int wid = threadIdx.x >> 5;
    const int lane = threadIdx.x & 31;
    const int wm = (wid & 3) * 32;
    const int wn = (wid >> 2) * 64;
    const int lr = lane >> 2;
    const int q8 = (lane & 3) << 3;

    int c[2][8][4];
#pragma unroll
    for (int i = 0; i < 2; i++)
#pragma unroll
        for (int j = 0; j < 8; j++)
#pragma unroll
            for (int t = 0; t < 4; t++) c[i][j][t] = 0;

#pragma unroll 2
    for (int k0 = 0; k0 < Cc; k0 += 32) {
        unsigned a[2][4];
#pragma unroll
        for (int mt = 0; mt < 2; mt++) {
            const int8_t* ap = g_xq + (bm + wm + mt * 16 + lr) * Cc + k0 + q8;
            uint2 lo = *(const uint2*)ap;
            uint2 hi = *(const uint2*)(ap + 8 * Cc);
            a[mt][0] = lo.x; a[mt][2] = lo.y;
            a[mt][1] = hi.x; a[mt][3] = hi.y;
        }
#pragma unroll
        for (int nt = 0; nt < 8; nt++) {
            uint2 bv = *(const uint2*)(g_wqkv + (bn + wn + nt * 8 + lr) * Cc + k0 + q8);
            unsigned bb[2] = {bv.x, bv.y};
            mma8(c[0][nt], a[0], bb);
            mma8(c[1][nt], a[1], bb);
        }
    }

    const float c1 = __ldg(al_a) * __ldg(al_w);
    const float iq = c1 / __ldg(al_q), ik = c1 / __ldg(al_k), iv = c1 / __ldg(al_v);
#pragma unroll
    for (int mt = 0; mt < 2; mt++)
#pragma unroll
        for (int nt = 0; nt < 8; nt++)
#pragma unroll
            for (int j = 0; j < 4; j++) {
                int row = bm + wm + mt * 16 + lr + ((j >> 1) << 3);
                int col = bn + wn + nt * 8 + ((lane & 3) << 1) + (j & 1);
                float f = (float)c[mt][nt][j];
                int b = row >> 11, n = row & (Nn - 1);
                int which = col / Cc;
                int cr = col - which * Cc;
                int h = cr >> 6, d = cr & 63;
                if (which == 0)
                    g_q[((b * Hh + h) * Nn + n) * Dd + PHYS32(d)] = (int8_t)q8i(f * iq);
                else if (which == 1)
                    g_k[((b * Hh + h) * Nn + n) * Dd + PHYS32(d)] = (int8_t)q8i(f * ik);
                else
                    g_vT[((b * Hh + h) * Dd + d) * Nn + PHYS32(n)] = (int8_t)q8i(f * iv);
            }
}

// ---------------- fused: QK^T -> quant -> softmax -> quant -> P@V -> quant -> g_o ----
#define LUTF_OFF (32 * SROW)          // 66048: float[256] exp LUT
#define LUT8_OFF (LUTF_OFF + 1024)    // per-warp int8 requant LUT (8 * 256)
#define SMEM_SZ  (LUT8_OFF + 8 * 256) // 69120

__global__ void __launch_bounds__(256, 2) attn_fused_k(
    const float* al_q, const float* al_k, const float* al_attn, const float* al_attn2,
    const float* al_v, const float* al_pa) {
    extern __shared__ int8_t s_s[];  // [32][SROW] scores/probs + LUTs
    const int bh = blockIdx.y;
    const int rb = blockIdx.x * 32;
    const int8_t* qp = g_q + bh * Nn * Dd;
    const int8_t* kp = g_k + bh * Nn * Dd;
    const int tid = threadIdx.x;
    const int wid = tid >> 5;
    const int lane = tid & 31;
    const int lr = lane >> 2;
    const int q8 = (lane & 3) << 3;
    const float aAttn = __ldg(al_attn);
    const float c2i = __ldg(al_q) * __ldg(al_k) * 0.125f / aAttn;

    // build float exp LUT: lutf[u] = exp2(k2 * (signed char)u)
    float* lutf = (float*)(s_s + LUTF_OFF);
    if (tid < 256) {
        const float k2 = aAttn * 1.44269504f;
        lutf[tid] = exp2f(k2 * (float)(char)tid);
    }

    // ---- Phase A: QK^T, quantize scores into smem (perm cols) ----
    unsigned a[2][2][4];
#pragma unroll
    for (int mt = 0; mt < 2; mt++)
#pragma unroll
        for (int ks = 0; ks < 2; ks++) {
            const int8_t* ap = qp + (rb + mt * 16 + lr) * Dd + ks * 32 + q8;
            uint2 lo = *(const uint2*)ap;
            uint2 hi = *(const uint2*)(ap + 8 * Dd);
            a[mt][ks][0] = lo.x; a[mt][ks][2] = lo.y;
            a[mt][ks][1] = hi.x; a[mt][ks][3] = hi.y;
        }

    const int nbase = wid * 256;
#pragma unroll 1
    for (int nc = 0; nc < 256; nc += 32) {
        int c[2][4][4];
#pragma unroll
        for (int i = 0; i < 2; i++)
#pragma unroll
            for (int j = 0; j < 4; j++)
#pragma unroll
                for (int t = 0; t < 4; t++) c[i][j][t] = 0;

#pragma unroll
        for (int nt = 0; nt < 4; nt++)
#pragma unroll
            for (int ks = 0; ks < 2; ks++) {
                uint2 bv = *(const uint2*)(kp + (nbase + nc + nt * 8 + lr) * Dd + ks * 32 + q8);
                unsigned bb[2] = {bv.x, bv.y};
                mma8(c[0][nt], a[0][ks], bb);
                mma8(c[1][nt], a[1][ks], bb);
            }
#pragma unroll
        for (int mt = 0; mt < 2; mt++)
#pragma unroll
            for (int nt = 0; nt < 4; nt++)
#pragma unroll
                for (int jj = 0; jj < 2; jj++) {
                    int row = mt * 16 + lr + jj * 8;
                    int col = nbase + nc + nt * 8 + ((lane & 3) << 1);
                    int pc = PHYS32(col);
                    char2 o;
                    o.x = (char)q8i((float)c[mt][nt][jj * 2 + 0] * c2i);
                    o.y = (char)q8i((float)c[mt][nt][jj * 2 + 1] * c2i);
                    *(char2*)(s_s + row * SROW + pc) = o;
                }
    }
    __syncthreads();

    // ---- Phase B: softmax per row via LUTs (order-invariant over perm cols) ----
    {
        const float a2 = __ldg(al_attn2);
        int8_t* lut8w = s_s + LUT8_OFF + wid * 256;
#pragma unroll 1
        for (int r = wid * 4; r < wid * 4 + 4; r++) {
            int8_t* srow = s_s + r * SROW;
            float s0 = 0.f, s1 = 0.f, s2 = 0.f, s3 = 0.f;
#pragma unroll
            for (int it = 0; it < 16; it++) {
                unsigned w = *(const unsigned*)(srow + lane * 4 + it * 128);
                s0 += lutf[w & 255];
                s1 += lutf[(w >> 8) & 255];
                s2 += lutf[(w >> 16) & 255];
                s3 += lutf[w >> 24];
            }
            float sum = (s0 + s1) + (s2 + s3);
#pragma unroll
            for (int off = 16; off; off >>= 1)
                sum += __shfl_xor_sync(0xffffffffu, sum, off);
            const float inv = 1.f / (sum * a2);

            // per-warp int8 requant LUT: lut8[u] = rint(min(lutf[u]*inv, 127))
            unsigned lo = 0, hi = 0;
#pragma unroll
            for (int j = 0; j < 8; j++) {
                int m = __float2int_rn(fminf(lutf[lane * 8 + j] * inv, 127.f));
                if (j < 4) lo |= (unsigned)(m & 255) << (8 * j);
                else       hi |= (unsigned)(m & 255) << (8 * (j - 4));
            }
            *(uint2*)(lut8w + lane * 8) = make_uint2(lo, hi);
            __syncwarp();
#pragma unroll
            for (int it = 0; it < 16; it++) {
                int8_t* p = srow + lane * 4 + it * 128;
                unsigned w = *(const unsigned*)p;
                unsigned r0 = (unsigned char)lut8w[w & 255];
                unsigned r1 = (unsigned char)lut8w[(w >> 8) & 255];
                unsigned r2 = (unsigned char)lut8w[(w >> 16) & 255];
                unsigned r3 = (unsigned char)lut8w[w >> 24];
                *(unsigned*)p = r0 | (r1 << 8) | (r2 << 16) | (r3 << 24);
            }
            __syncwarp();
        }
    }
    __syncthreads();

    // ---- Phase C: out = P @ V (A from smem LDS.64, B = vT LDG.64), requant -> g_o ----
    {
        const int8_t* Vt = g_vT + bh * Dd * Nn;
        const int wm2 = (wid & 1) * 16;
        const int wn2 = (wid >> 1) * 16;
        int c[2][4];
#pragma unroll
        for (int i = 0; i < 2; i++)
#pragma unroll
            for (int t = 0; t < 4; t++) c[i][t] = 0;

#pragma unroll 2
        for (int k0 = 0; k0 < Nn; k0 += 32) {
            unsigned af[4];
            const int8_t* ap = s_s + (wm2 + lr) * SROW + k0 + q8;
            uint2 lo = *(const uint2*)ap;
            uint2 hi = *(const uint2*)(ap + 8 * SROW);
            af[0] = lo.x; af[2] = lo.y;
            af[1] = hi.x; af[3] = hi.y;
#pragma unroll
            for (int nt = 0; nt < 2; nt++) {
                uint2 bv = *(const uint2*)(Vt + (wn2 + nt * 8 + lr) * Nn + k0 + q8);
                unsigned bb[2] = {bv.x, bv.y};
                mma8(c[nt], af, bb);
            }
        }

        const float c3 = __ldg(al_attn2) * __ldg(al_v);
        const float ipa = c3 / __ldg(al_pa);
        const int b = bh / Hh, h = bh % Hh;
#pragma unroll
        for (int nt = 0; nt < 2; nt++)
#pragma unroll
            for (int j = 0; j < 4; j++) {
                int n = rb + wm2 + lr + ((j >> 1) << 3);
                int d = wn2 + nt * 8 + ((lane & 3) << 1) + (j & 1);
                g_o[(b * Nn + n) * Cc + h * Dd + PHYS32(d)] =
                    (int8_t)q8i((float)c[nt][j] * ipa);
            }
    }
}

// ---------------- GEMM2: final projection + bias -> fp32 out ----------------
__global__ void __launch_bounds__(256) gemm_proj_k(
    float* __restrict__ out, const float* __restrict__ bias,
    const float* al_pa, const float* al_pw) {
    const int bm = blockIdx.y * 128;
    const int bn = blockIdx.x * 128;
    const int wid = threadIdx.x >> 5;
    const int lane = threadIdx.x & 31;
    const int wm = (wid & 3) * 32;
    const int wn = (wid >> 2) * 64;
    const int lr = lane >> 2;
    const int q8 = (lane & 3) << 3;

    int c[2][8][4];
#pragma unroll
    for (int i = 0; i < 2; i++)
#pragma unroll
        for (int j = 0; j < 8; j++)
#pragma unroll
            for (int t = 0; t < 4; t++) c[i][j][t] = 0;

#pragma unroll 2
    for (int k0 = 0; k0 < Cc; k0 += 32) {
        unsigned a[2][4];
#pragma unroll
        for (int mt = 0; mt < 2; mt++) {
            const int8_t* ap = g_o + (bm + wm + mt * 16 + lr) * Cc + k0 + q8;
            uint2 lo = *(const uint2*)ap;
            uint2 hi = *(const uint2*)(ap + 8 * Cc);
            a[mt][0] = lo.x; a[mt][2] = lo.y;
            a[mt][1] = hi.x; a[mt][3] = hi.y;
        }
#pragma unroll
        for (int nt = 0; nt < 8; nt++) {
            uint2 bv = *(const uint2*)(g_wproj + (bn + wn + nt * 8 + lr) * Cc + k0 + q8);
            unsigned bb[2] = {bv.x, bv.y};
            mma8(c[0][nt], a[0], bb);
            mma8(c[1][nt], a[1], bb);
        }
    }

    const float sc = __ldg(al_pa) * __ldg(al_pw);
#pragma unroll
    for (int mt = 0; mt < 2; mt++)
#pragma unroll
        for (int nt = 0; nt < 8; nt++)
#pragma unroll
            for (int j = 0; j < 4; j++) {
                int row = bm + wm + mt * 16 + lr + ((j >> 1) << 3);
                int col = bn + wn + nt * 8 + ((lane & 3) << 1) + (j & 1);
                out[row * Cc + col] = (float)c[mt][nt][j] * sc + __ldg(bias + col);
            }
}

extern "C" void kernel_launch(void* const* d_in, const int* in_sizes, int n_in,
                              void* d_out, int out_size) {
    const float* x        = (const float*)d_in[0];
    const float* w_qkv    = (const float*)d_in[1];
    const float* w_proj   = (const float*)d_in[2];
    const float* b_proj   = (const float*)d_in[3];
    const float* a_qkv_w  = (const float*)d_in[4];
    const float* a_qkv_a  = (const float*)d_in[5];
    const float* a_proj_w = (const float*)d_in[6];
    const float* a_proj_a = (const float*)d_in[7];
    const float* a_q      = (const float*)d_in[8];
    const float* a_k      = (const float*)d_in[9];
    const float* a_v      = (const float*)d_in[10];
    const float* a_attn   = (const float*)d_in[11];
    const float* a_attn2  = (const float*)d_in[12];
    float* out = (float*)d_out;

    quant_x_k<<<BN * Cc / 4 / 256, 256>>>(x, a_qkv_a);
    quant_wqkv_k<<<C3 * Cc / 4 / 256, 256>>>(w_qkv, a_qkv_w);
    quant_wproj_k<<<Cc * Cc / 4 / 256, 256>>>(w_proj, a_proj_w);

    gemm_qkv_k<<<dim3(C3 / 128, BN / 128), 256>>>(a_qkv_a, a_qkv_w, a_q, a_k, a_v);

    cudaFuncSetAttribute(attn_fused_k, cudaFuncAttributeMaxDynamicSharedMemorySize, SMEM_SZ);
    attn_fused_k<<<dim3(Nn / 32, BHh), 256, SMEM_SZ>>>(a_q, a_k, a_attn, a_attn2, a_v, a_proj_a);

    gemm_proj_k<<<dim3(Cc / 128, BN / 128), 256>>>(out, b_proj, a_proj_a, a_proj_w);
}